// round 1
// baseline (speedup 1.0000x reference)
#include <cuda_runtime.h>
#include <math.h>

#define BATCH   2
#define SEQ     2048
#define HEADS   12
#define DH      64
#define DMODEL  768
#define MROWS   (BATCH * SEQ)    // 4096
#define WIN     128

// ---------------- scratch (no allocation allowed; __device__ globals) ----------------
__device__ float g_qkin[MROWS * DMODEL];
__device__ float g_q[MROWS * DMODEL];
__device__ float g_k[MROWS * DMODEL];
__device__ float g_v[MROWS * DMODEL];
__device__ float g_ctx[MROWS * DMODEL];

// ---------------- RoPE (rotate-half, applied to raw hidden states) ----------------
__global__ void rope_kernel(const float* __restrict__ x, float* __restrict__ y) {
    const int NP = MROWS * DMODEL / 2;
    int idx = blockIdx.x * blockDim.x + threadIdx.x;
    if (idx >= NP) return;
    int row = idx / (DMODEL / 2);
    int rem = idx % (DMODEL / 2);
    int h = rem / 32;
    int i = rem % 32;            // half-dim index 0..31
    int s = row % SEQ;
    float inv = powf(10000.0f, -(float)i / 32.0f);
    float ang = (float)s * inv;
    float sn, cs;
    sincosf(ang, &sn, &cs);
    int base = row * DMODEL + h * DH;
    float x1 = x[base + i];
    float x2 = x[base + 32 + i];
    y[base + i]      = x1 * cs - x2 * sn;
    y[base + 32 + i] = x2 * cs + x1 * sn;
}

// ---------------- fp32 SGEMM with per-column bias: C[M,N] = A[M,K] @ B[K,N] + bias ----------------
#define BM 128
#define BN 128
#define BK 16
#define TM 8
#define TN 8

__global__ __launch_bounds__(256) void sgemm_bias(
    const float* __restrict__ A, const float* __restrict__ Bm,
    const float* __restrict__ bias, float* __restrict__ C,
    int M, int N, int K)
{
    __shared__ float As[BK][BM + 4];
    __shared__ float Bs[BK][BN + 4];

    int tid = threadIdx.x;
    int bx = blockIdx.x, by = blockIdx.y;
    const float* Ablk = A + (size_t)by * BM * K;
    const float* Bblk = Bm + (size_t)bx * BN;

    int arow  = tid >> 2;        // 0..63
    int acol4 = tid & 3;         // 0..3  (cols acol4*4 .. +3)
    int brow  = tid >> 5;        // 0..7
    int bcol4 = tid & 31;        // 0..31 (cols bcol4*4 .. +3)

    int ty = tid >> 4;           // 0..15 -> row-tile
    int tx = tid & 15;           // 0..15 -> col-tile

    float acc[TM][TN] = {};

    for (int k0 = 0; k0 < K; k0 += BK) {
        // A tile -> transposed As[k][m]
#pragma unroll
        for (int rr = 0; rr < 2; rr++) {
            int r = arow + rr * 64;
            float4 v = *(const float4*)(Ablk + (size_t)r * K + k0 + acol4 * 4);
            As[acol4 * 4 + 0][r] = v.x;
            As[acol4 * 4 + 1][r] = v.y;
            As[acol4 * 4 + 2][r] = v.z;
            As[acol4 * 4 + 3][r] = v.w;
        }
        // B tile -> Bs[k][n]
#pragma unroll
        for (int rr = 0; rr < 2; rr++) {
            int r = brow + rr * 8;
            float4 v = *(const float4*)(Bblk + (size_t)(k0 + r) * N + bcol4 * 4);
            *(float4*)&Bs[r][bcol4 * 4] = v;
        }
        __syncthreads();

#pragma unroll
        for (int k = 0; k < BK; k++) {
            float ar[TM], br[TN];
#pragma unroll
            for (int i = 0; i < TM; i++) ar[i] = As[k][ty * TM + i];
#pragma unroll
            for (int j = 0; j < TN; j++) br[j] = Bs[k][tx * TN + j];
#pragma unroll
            for (int i = 0; i < TM; i++)
#pragma unroll
                for (int j = 0; j < TN; j++)
                    acc[i][j] += ar[i] * br[j];
        }
        __syncthreads();
    }

#pragma unroll
    for (int i = 0; i < TM; i++) {
        int r = by * BM + ty * TM + i;
#pragma unroll
        for (int j = 0; j < TN; j += 4) {
            int c = bx * BN + tx * TN + j;
            float4 o;
            o.x = acc[i][j + 0] + bias[c + 0];
            o.y = acc[i][j + 1] + bias[c + 1];
            o.z = acc[i][j + 2] + bias[c + 2];
            o.w = acc[i][j + 3] + bias[c + 3];
            *(float4*)(C + (size_t)r * N + c) = o;
        }
    }
}

// ---------------- sliding-window attention ----------------
// Block = (q-tile of 64, head, batch). Full 64x320 score strip in smem;
// two register-tiled passes (scores, then P@V). Exact vs reference: masked
// entries get -1e30 -> exp underflows to 0 (same as score-1e9 in fp32 softmax).
#define BQ   64
#define KT   64
#define NKT  5
#define KVPAD 65         // sKV row stride (floats)
#define SSTR 321         // sS row stride (floats)

__global__ __launch_bounds__(256) void attn_kernel(
    const float* __restrict__ Q, const float* __restrict__ K,
    const float* __restrict__ V, float* __restrict__ O)
{
    extern __shared__ float sm[];
    float* sQ   = sm;                        // 64*64
    float* sKV  = sQ + BQ * DH;              // 64*65
    float* sS   = sKV + KT * KVPAD;          // 64*321
    float* sSum = sS + BQ * SSTR;            // 64

    int tid = threadIdx.x;
    int qt = blockIdx.x, h = blockIdx.y, b = blockIdx.z;
    int q0 = qt * BQ;
    int kstart = q0 - 2 * WIN + WIN; // q0 - 128
    kstart = q0 - WIN;
    const int rowbase = b * SEQ;
    const int colbase = h * DH;

    // load Q tile (float4, coalesced)
    for (int p = tid; p < BQ * DH / 4; p += 256) {
        int r = p / (DH / 4);
        int c4 = p % (DH / 4);
        float4 v = *(const float4*)(Q + (size_t)(rowbase + q0 + r) * DMODEL + colbase + c4 * 4);
        *(float4*)&sQ[r * DH + c4 * 4] = v;
    }

    int tr = tid >> 4;   // 0..15
    int tc = tid & 15;   // 0..15

    // ---- pass 1: scores into strip ----
    for (int kt = 0; kt < NKT; kt++) {
        __syncthreads();
        // load K tile (guard OOB keys with zeros)
        for (int p = tid; p < KT * DH / 4; p += 256) {
            int c = p / (DH / 4);
            int d4 = p % (DH / 4);
            int j = kstart + kt * KT + c;
            float4 v = make_float4(0.f, 0.f, 0.f, 0.f);
            if (j >= 0 && j < SEQ)
                v = *(const float4*)(K + (size_t)(rowbase + j) * DMODEL + colbase + d4 * 4);
            sKV[c * KVPAD + d4 * 4 + 0] = v.x;
            sKV[c * KVPAD + d4 * 4 + 1] = v.y;
            sKV[c * KVPAD + d4 * 4 + 2] = v.z;
            sKV[c * KVPAD + d4 * 4 + 3] = v.w;
        }
        __syncthreads();

        float acc[4][4] = {};
#pragma unroll 8
        for (int d = 0; d < DH; d++) {
            float qr[4], kr[4];
#pragma unroll
            for (int i = 0; i < 4; i++) qr[i] = sQ[(tr * 4 + i) * DH + d];
#pragma unroll
            for (int j = 0; j < 4; j++) kr[j] = sKV[(tc * 4 + j) * KVPAD + d];
#pragma unroll
            for (int i = 0; i < 4; i++)
#pragma unroll
                for (int j = 0; j < 4; j++)
                    acc[i][j] += qr[i] * kr[j];
        }
#pragma unroll
        for (int i = 0; i < 4; i++) {
            int r = tr * 4 + i;
            int ii = q0 + r;
#pragma unroll
            for (int j = 0; j < 4; j++) {
                int c = tc * 4 + j;
                int jj = kstart + kt * KT + c;
                bool ok = (jj >= 0) && (jj < SEQ) && (jj > ii - WIN) && (jj < ii + WIN);
                sS[r * SSTR + kt * KT + c] = ok ? acc[i][j] * 0.125f : -1e30f;
            }
        }
    }
    __syncthreads();

    // ---- softmax per row (8 warps x 8 rows each) ----
    int warp = tid >> 5, lane = tid & 31;
    for (int r = warp; r < BQ; r += 8) {
        float m = -1e30f;
        for (int c = lane; c < NKT * KT; c += 32)
            m = fmaxf(m, sS[r * SSTR + c]);
#pragma unroll
        for (int o = 16; o > 0; o >>= 1)
            m = fmaxf(m, __shfl_xor_sync(0xffffffffu, m, o));
        float s = 0.f;
        for (int c = lane; c < NKT * KT; c += 32) {
            float p = expf(sS[r * SSTR + c] - m);
            sS[r * SSTR + c] = p;
            s += p;
        }
#pragma unroll
        for (int o = 16; o > 0; o >>= 1)
            s += __shfl_xor_sync(0xffffffffu, s, o);
        if (lane == 0) sSum[r] = s;
    }
    __syncthreads();

    // ---- pass 2: ctx = P @ V ----
    float acc2[4][4] = {};  // rows tr*4+i, dims tc*4+j
    for (int kt = 0; kt < NKT; kt++) {
        __syncthreads();
        for (int p = tid; p < KT * DH / 4; p += 256) {
            int c = p / (DH / 4);
            int d4 = p % (DH / 4);
            int j = kstart + kt * KT + c;
            float4 v = make_float4(0.f, 0.f, 0.f, 0.f);
            if (j >= 0 && j < SEQ)
                v = *(const float4*)(V + (size_t)(rowbase + j) * DMODEL + colbase + d4 * 4);
            sKV[c * KVPAD + d4 * 4 + 0] = v.x;
            sKV[c * KVPAD + d4 * 4 + 1] = v.y;
            sKV[c * KVPAD + d4 * 4 + 2] = v.z;
            sKV[c * KVPAD + d4 * 4 + 3] = v.w;
        }
        __syncthreads();

#pragma unroll 8
        for (int c = 0; c < KT; c++) {
            float pr[4], vr[4];
#pragma unroll
            for (int i = 0; i < 4; i++) pr[i] = sS[(tr * 4 + i) * SSTR + kt * KT + c];
#pragma unroll
            for (int j = 0; j < 4; j++) vr[j] = sKV[c * KVPAD + tc * 4 + j];
#pragma unroll
            for (int i = 0; i < 4; i++)
#pragma unroll
                for (int j = 0; j < 4; j++)
                    acc2[i][j] += pr[i] * vr[j];
        }
    }

#pragma unroll
    for (int i = 0; i < 4; i++) {
        int r = tr * 4 + i;
        float inv = 1.0f / sSum[r];
#pragma unroll
        for (int j = 0; j < 4; j++) {
            O[(size_t)(rowbase + q0 + r) * DMODEL + colbase + tc * 4 + j] = acc2[i][j] * inv;
        }
    }
}

// ---------------- launcher ----------------
extern "C" void kernel_launch(void* const* d_in, const int* in_sizes, int n_in,
                              void* d_out, int out_size)
{
    const float* hid = (const float*)d_in[0];
    const float* Wq  = (const float*)d_in[1];
    const float* bq  = (const float*)d_in[2];
    const float* Wk  = (const float*)d_in[3];
    const float* bk  = (const float*)d_in[4];
    const float* Wv  = (const float*)d_in[5];
    const float* bv  = (const float*)d_in[6];
    const float* Wo  = (const float*)d_in[7];
    const float* bo  = (const float*)d_in[8];
    float* out = (float*)d_out;

    float *qkin, *q, *k, *v, *ctx;
    cudaGetSymbolAddress((void**)&qkin, g_qkin);
    cudaGetSymbolAddress((void**)&q,    g_q);
    cudaGetSymbolAddress((void**)&k,    g_k);
    cudaGetSymbolAddress((void**)&v,    g_v);
    cudaGetSymbolAddress((void**)&ctx,  g_ctx);

    // RoPE
    {
        int NP = MROWS * DMODEL / 2;
        rope_kernel<<<(NP + 255) / 256, 256>>>(hid, qkin);
    }

    // Q/K/V projections
    {
        dim3 grid(DMODEL / BN, MROWS / BM);
        sgemm_bias<<<grid, 256>>>(qkin, Wq, bq, q, MROWS, DMODEL, DMODEL);
        sgemm_bias<<<grid, 256>>>(qkin, Wk, bk, k, MROWS, DMODEL, DMODEL);
        sgemm_bias<<<grid, 256>>>(hid,  Wv, bv, v, MROWS, DMODEL, DMODEL);
    }

    // attention
    {
        int smem = (BQ * DH + KT * KVPAD + BQ * SSTR + BQ) * (int)sizeof(float);
        cudaFuncSetAttribute(attn_kernel, cudaFuncAttributeMaxDynamicSharedMemorySize, smem);
        dim3 grid(SEQ / BQ, HEADS, BATCH);
        attn_kernel<<<grid, 256, smem>>>(q, k, v, ctx);
    }

    // output projection
    {
        dim3 grid(DMODEL / BN, MROWS / BM);
        sgemm_bias<<<grid, 256>>>(ctx, Wo, bo, out, MROWS, DMODEL, DMODEL);
    }
}

// round 3
// speedup vs baseline: 2.1963x; 2.1963x over previous
#include <cuda_runtime.h>
#include <cuda_bf16.h>
#include <math.h>
#include <stdint.h>

#define BATCH   2
#define SEQ     2048
#define HEADS   12
#define DH      64
#define DMODEL  768
#define MROWS   (BATCH * SEQ)    // 4096
#define WIN     128

// ---------------- scratch (__device__ globals; no allocation allowed) ----------------
__device__ __align__(256) float g_q[MROWS * DMODEL];
__device__ __align__(256) float g_k[MROWS * DMODEL];
__device__ __align__(256) float g_v[MROWS * DMODEL];
__device__ __align__(256) float g_ctx[MROWS * DMODEL];
__device__ __align__(256) __nv_bfloat16 g_qk_h[MROWS * DMODEL];
__device__ __align__(256) __nv_bfloat16 g_qk_l[MROWS * DMODEL];
__device__ __align__(256) __nv_bfloat16 g_hid_h[MROWS * DMODEL];
__device__ __align__(256) __nv_bfloat16 g_hid_l[MROWS * DMODEL];
__device__ __align__(256) __nv_bfloat16 g_ctx_h[MROWS * DMODEL];
__device__ __align__(256) __nv_bfloat16 g_ctx_l[MROWS * DMODEL];
__device__ __align__(256) __nv_bfloat16 g_wq_h[DMODEL * DMODEL];
__device__ __align__(256) __nv_bfloat16 g_wq_l[DMODEL * DMODEL];
__device__ __align__(256) __nv_bfloat16 g_wk_h[DMODEL * DMODEL];
__device__ __align__(256) __nv_bfloat16 g_wk_l[DMODEL * DMODEL];
__device__ __align__(256) __nv_bfloat16 g_wv_h[DMODEL * DMODEL];
__device__ __align__(256) __nv_bfloat16 g_wv_l[DMODEL * DMODEL];
__device__ __align__(256) __nv_bfloat16 g_wo_h[DMODEL * DMODEL];
__device__ __align__(256) __nv_bfloat16 g_wo_l[DMODEL * DMODEL];

// ---------------- PTX helpers ----------------
__device__ __forceinline__ uint32_t smem_u32(const void* p) {
    uint32_t a;
    asm("{ .reg .u64 t; cvta.to.shared.u64 t, %1; cvt.u32.u64 %0, t; }" : "=r"(a) : "l"(p));
    return a;
}
__device__ __forceinline__ void cpa16(uint32_t dst, const void* src) {
    asm volatile("cp.async.cg.shared.global [%0], [%1], 16;" :: "r"(dst), "l"(src));
}
#define CP_COMMIT() asm volatile("cp.async.commit_group;")
#define CP_WAIT(N)  asm volatile("cp.async.wait_group %0;" :: "n"(N))

__device__ __forceinline__ void ldsm4(uint32_t& r0, uint32_t& r1, uint32_t& r2, uint32_t& r3,
                                      uint32_t addr) {
    asm volatile("ldmatrix.sync.aligned.m8n8.x4.shared.b16 {%0,%1,%2,%3}, [%4];"
                 : "=r"(r0), "=r"(r1), "=r"(r2), "=r"(r3) : "r"(addr));
}
__device__ __forceinline__ void mma16816(float* d, const uint32_t* a, uint32_t b0, uint32_t b1) {
    asm volatile(
        "mma.sync.aligned.m16n8k16.row.col.f32.bf16.bf16.f32 "
        "{%0,%1,%2,%3}, {%4,%5,%6,%7}, {%8,%9}, {%0,%1,%2,%3};"
        : "+f"(d[0]), "+f"(d[1]), "+f"(d[2]), "+f"(d[3])
        : "r"(a[0]), "r"(a[1]), "r"(a[2]), "r"(a[3]), "r"(b0), "r"(b1));
}

// ---------------- conversion kernels ----------------
__device__ __forceinline__ void split_one(float x, __nv_bfloat16& h, __nv_bfloat16& l) {
    h = __float2bfloat16(x);
    l = __float2bfloat16(x - __bfloat162float(h));
}

__global__ void rope_split_kernel(const float* __restrict__ x,
                                  __nv_bfloat16* __restrict__ oh,
                                  __nv_bfloat16* __restrict__ ol) {
    const int NP = MROWS * DMODEL / 2;
    int idx = blockIdx.x * blockDim.x + threadIdx.x;
    if (idx >= NP) return;
    int row = idx / (DMODEL / 2);
    int rem = idx % (DMODEL / 2);
    int h = rem / 32;
    int i = rem % 32;
    int s = row % SEQ;
    float inv = powf(10000.0f, -(float)i / 32.0f);
    float sn, cs;
    sincosf((float)s * inv, &sn, &cs);
    int base = row * DMODEL + h * DH;
    float x1 = x[base + i];
    float x2 = x[base + 32 + i];
    float y1 = x1 * cs - x2 * sn;
    float y2 = x2 * cs + x1 * sn;
    __nv_bfloat16 hh, ll;
    split_one(y1, hh, ll); oh[base + i] = hh;      ol[base + i] = ll;
    split_one(y2, hh, ll); oh[base + 32 + i] = hh; ol[base + 32 + i] = ll;
}

__global__ void split_kernel(const float* __restrict__ x,
                             __nv_bfloat16* __restrict__ oh,
                             __nv_bfloat16* __restrict__ ol) {
    int idx = blockIdx.x * blockDim.x + threadIdx.x;
    if (idx >= MROWS * DMODEL) return;
    __nv_bfloat16 h, l;
    split_one(x[idx], h, l);
    oh[idx] = h; ol[idx] = l;
}

// W[k][n] (row-major KxN) -> out[n][k] split into hi/lo
__global__ void wtrans_split(const float* __restrict__ W,
                             __nv_bfloat16* __restrict__ oh,
                             __nv_bfloat16* __restrict__ ol) {
    __shared__ float t[32][33];
    int nb = blockIdx.x * 32, kb = blockIdx.y * 32;
    int tx = threadIdx.x, ty = threadIdx.y;   // (32, 8)
#pragma unroll
    for (int r = 0; r < 32; r += 8)
        t[ty + r][tx] = W[(size_t)(kb + ty + r) * DMODEL + nb + tx];
    __syncthreads();
#pragma unroll
    for (int r = 0; r < 32; r += 8) {
        float x = t[tx][ty + r];
        __nv_bfloat16 h, l;
        split_one(x, h, l);
        size_t o = (size_t)(nb + ty + r) * DMODEL + kb + tx;
        oh[o] = h; ol[o] = l;
    }
}

// ---------------- mma.sync bf16x3 GEMM: C[M,768] = A @ B^T + bias ----------------
// Block tile 128x128, BK=64 (128B rows, XOR-8 swizzle). 8 warps, warp tile 32x64.
#define GBM 128
#define GBN 128
#define GK  768
#define GKC 64
#define NCH (GK / GKC)           // 12
#define MAT_BYTES (128 * 128)    // 16384 (one 128-row x 128B matrix)
#define STAGE_BYTES (4 * MAT_BYTES)   // Ah, Al, Bh, Bl
#define GEMM_SMEM (2 * STAGE_BYTES)   // 131072

struct GemmArgs {
    const __nv_bfloat16* Ah[3];
    const __nv_bfloat16* Al[3];
    const __nv_bfloat16* Bh[3];
    const __nv_bfloat16* Bl[3];
    const float* bias[3];
    float* C[3];
};

__device__ __forceinline__ void load_chunk(
    uint32_t st,
    const __nv_bfloat16* __restrict__ Ah, const __nv_bfloat16* __restrict__ Al,
    const __nv_bfloat16* __restrict__ Bh, const __nv_bfloat16* __restrict__ Bl,
    int m0, int n0, int kc, int tid)
{
    int k0 = kc * GKC;
#pragma unroll
    for (int i = 0; i < 4; i++) {
        int u = tid + i * 256;
        int r = u >> 3, c = u & 7;
        uint32_t off = (uint32_t)(r * 128) + (uint32_t)((c ^ (r & 7)) << 4);
        size_t ga = (size_t)(m0 + r) * GK + k0 + c * 8;
        size_t gb = (size_t)(n0 + r) * GK + k0 + c * 8;
        cpa16(st + off,                 Ah + ga);
        cpa16(st + MAT_BYTES + off,     Al + ga);
        cpa16(st + 2 * MAT_BYTES + off, Bh + gb);
        cpa16(st + 3 * MAT_BYTES + off, Bl + gb);
    }
}

__global__ __launch_bounds__(256, 1) void gemm_mma(GemmArgs args)
{
    extern __shared__ __align__(1024) char sm[];
    uint32_t sb = smem_u32(sm);
    int tid = threadIdx.x, lane = tid & 31, warp = tid >> 5;
    int wm = warp >> 1, wn = warp & 1;        // 4 x 2 warp grid
    int z = blockIdx.z;
    int m0 = blockIdx.y * GBM, n0 = blockIdx.x * GBN;

    const __nv_bfloat16* Ah = args.Ah[z];
    const __nv_bfloat16* Al = args.Al[z];
    const __nv_bfloat16* Bh = args.Bh[z];
    const __nv_bfloat16* Bl = args.Bl[z];
    const float* bias = args.bias[z];
    float* C = args.C[z];

    float acc[2][8][4];
#pragma unroll
    for (int a = 0; a < 2; a++)
#pragma unroll
        for (int b = 0; b < 8; b++)
#pragma unroll
            for (int c = 0; c < 4; c++) acc[a][b][c] = 0.f;

    load_chunk(sb, Ah, Al, Bh, Bl, m0, n0, 0, tid);
    CP_COMMIT();

    for (int kc = 0; kc < NCH; kc++) {
        if (kc + 1 < NCH) {
            load_chunk(sb + ((kc + 1) & 1) * STAGE_BYTES, Ah, Al, Bh, Bl, m0, n0, kc + 1, tid);
            CP_COMMIT();
            CP_WAIT(1);
        } else {
            CP_WAIT(0);
        }
        __syncthreads();

        uint32_t base = sb + (kc & 1) * STAGE_BYTES;
#pragma unroll
        for (int ks = 0; ks < 4; ks++) {
            int c0 = ks * 2;    // 16B-chunk index of k-step start
            uint32_t ah[2][4], al[2][4];
#pragma unroll
            for (int mt = 0; mt < 2; mt++) {
                int row = wm * 32 + mt * 16 + (lane & 15);
                int ch = c0 + (lane >> 4);
                uint32_t off = (uint32_t)(row * 128) + (uint32_t)(((ch ^ (row & 7))) << 4);
                ldsm4(ah[mt][0], ah[mt][1], ah[mt][2], ah[mt][3], base + off);
                ldsm4(al[mt][0], al[mt][1], al[mt][2], al[mt][3], base + MAT_BYTES + off);
            }
            uint32_t bh[4][4], bl[4][4];
#pragma unroll
            for (int p = 0; p < 4; p++) {
                int row = wn * 64 + p * 16 + (lane & 7) + ((lane >> 4) << 3);
                int ch = c0 + ((lane >> 3) & 1);
                uint32_t off = (uint32_t)(row * 128) + (uint32_t)(((ch ^ (row & 7))) << 4);
                ldsm4(bh[p][0], bh[p][1], bh[p][2], bh[p][3], base + 2 * MAT_BYTES + off);
                ldsm4(bl[p][0], bl[p][1], bl[p][2], bl[p][3], base + 3 * MAT_BYTES + off);
            }
#pragma unroll
            for (int mt = 0; mt < 2; mt++) {
#pragma unroll
                for (int p = 0; p < 4; p++) {
                    mma16816(acc[mt][2 * p],     ah[mt], bh[p][0], bh[p][1]);
                    mma16816(acc[mt][2 * p],     al[mt], bh[p][0], bh[p][1]);
                    mma16816(acc[mt][2 * p],     ah[mt], bl[p][0], bl[p][1]);
                    mma16816(acc[mt][2 * p + 1], ah[mt], bh[p][2], bh[p][3]);
                    mma16816(acc[mt][2 * p + 1], al[mt], bh[p][2], bh[p][3]);
                    mma16816(acc[mt][2 * p + 1], ah[mt], bl[p][2], bl[p][3]);
                }
            }
        }
        __syncthreads();
    }

    // epilogue: D fragment c0,c1 -> row t/4; c2,c3 -> row t/4+8; cols 2*(t%4)+{0,1}
#pragma unroll
    for (int mt = 0; mt < 2; mt++) {
        int row = m0 + wm * 32 + mt * 16 + (lane >> 2);
#pragma unroll
        for (int nt = 0; nt < 8; nt++) {
            int col = n0 + wn * 64 + nt * 8 + 2 * (lane & 3);
            float b0 = bias[col], b1 = bias[col + 1];
            float2 v0 = make_float2(acc[mt][nt][0] + b0, acc[mt][nt][1] + b1);
            float2 v1 = make_float2(acc[mt][nt][2] + b0, acc[mt][nt][3] + b1);
            *(float2*)(C + (size_t)row * DMODEL + col) = v0;
            *(float2*)(C + (size_t)(row + 8) * DMODEL + col) = v1;
        }
    }
}

// ---------------- sliding-window attention (fp32) ----------------
#define BQ   64
#define KT   64
#define NKT  5
#define KVPAD 65
#define SSTR 321

__global__ __launch_bounds__(256) void attn_kernel(
    const float* __restrict__ Q, const float* __restrict__ K,
    const float* __restrict__ V, float* __restrict__ O)
{
    extern __shared__ float smf[];
    float* sQ   = smf;
    float* sKV  = sQ + BQ * DH;
    float* sS   = sKV + KT * KVPAD;
    float* sSum = sS + BQ * SSTR;

    int tid = threadIdx.x;
    int qt = blockIdx.x, h = blockIdx.y, b = blockIdx.z;
    int q0 = qt * BQ;
    int kstart = q0 - WIN;
    const int rowbase = b * SEQ;
    const int colbase = h * DH;

    for (int p = tid; p < BQ * DH / 4; p += 256) {
        int r = p / (DH / 4);
        int c4 = p % (DH / 4);
        float4 v = *(const float4*)(Q + (size_t)(rowbase + q0 + r) * DMODEL + colbase + c4 * 4);
        *(float4*)&sQ[r * DH + c4 * 4] = v;
    }

    int tr = tid >> 4;
    int tc = tid & 15;

    for (int kt = 0; kt < NKT; kt++) {
        __syncthreads();
        for (int p = tid; p < KT * DH / 4; p += 256) {
            int c = p / (DH / 4);
            int d4 = p % (DH / 4);
            int j = kstart + kt * KT + c;
            float4 v = make_float4(0.f, 0.f, 0.f, 0.f);
            if (j >= 0 && j < SEQ)
                v = *(const float4*)(K + (size_t)(rowbase + j) * DMODEL + colbase + d4 * 4);
            sKV[c * KVPAD + d4 * 4 + 0] = v.x;
            sKV[c * KVPAD + d4 * 4 + 1] = v.y;
            sKV[c * KVPAD + d4 * 4 + 2] = v.z;
            sKV[c * KVPAD + d4 * 4 + 3] = v.w;
        }
        __syncthreads();

        float acc[4][4] = {};
#pragma unroll 8
        for (int d = 0; d < DH; d++) {
            float qr[4], kr[4];
#pragma unroll
            for (int i = 0; i < 4; i++) qr[i] = sQ[(tr * 4 + i) * DH + d];
#pragma unroll
            for (int j = 0; j < 4; j++) kr[j] = sKV[(tc * 4 + j) * KVPAD + d];
#pragma unroll
            for (int i = 0; i < 4; i++)
#pragma unroll
                for (int j = 0; j < 4; j++)
                    acc[i][j] += qr[i] * kr[j];
        }
#pragma unroll
        for (int i = 0; i < 4; i++) {
            int r = tr * 4 + i;
            int ii = q0 + r;
#pragma unroll
            for (int j = 0; j < 4; j++) {
                int c = tc * 4 + j;
                int jj = kstart + kt * KT + c;
                bool ok = (jj >= 0) && (jj < SEQ) && (jj > ii - WIN) && (jj < ii + WIN);
                sS[r * SSTR + kt * KT + c] = ok ? acc[i][j] * 0.125f : -1e30f;
            }
        }
    }
    __syncthreads();

    int warp = tid >> 5, lane = tid & 31;
    for (int r = warp; r < BQ; r += 8) {
        float m = -1e30f;
        for (int c = lane; c < NKT * KT; c += 32)
            m = fmaxf(m, sS[r * SSTR + c]);
#pragma unroll
        for (int o = 16; o > 0; o >>= 1)
            m = fmaxf(m, __shfl_xor_sync(0xffffffffu, m, o));
        float s = 0.f;
        for (int c = lane; c < NKT * KT; c += 32) {
            float p = expf(sS[r * SSTR + c] - m);
            sS[r * SSTR + c] = p;
            s += p;
        }
#pragma unroll
        for (int o = 16; o > 0; o >>= 1)
            s += __shfl_xor_sync(0xffffffffu, s, o);
        if (lane == 0) sSum[r] = s;
    }
    __syncthreads();

    float acc2[4][4] = {};
    for (int kt = 0; kt < NKT; kt++) {
        __syncthreads();
        for (int p = tid; p < KT * DH / 4; p += 256) {
            int c = p / (DH / 4);
            int d4 = p % (DH / 4);
            int j = kstart + kt * KT + c;
            float4 v = make_float4(0.f, 0.f, 0.f, 0.f);
            if (j >= 0 && j < SEQ)
                v = *(const float4*)(V + (size_t)(rowbase + j) * DMODEL + colbase + d4 * 4);
            sKV[c * KVPAD + d4 * 4 + 0] = v.x;
            sKV[c * KVPAD + d4 * 4 + 1] = v.y;
            sKV[c * KVPAD + d4 * 4 + 2] = v.z;
            sKV[c * KVPAD + d4 * 4 + 3] = v.w;
        }
        __syncthreads();

#pragma unroll 8
        for (int c = 0; c < KT; c++) {
            float pr[4], vr[4];
#pragma unroll
            for (int i = 0; i < 4; i++) pr[i] = sS[(tr * 4 + i) * SSTR + kt * KT + c];
#pragma unroll
            for (int j = 0; j < 4; j++) vr[j] = sKV[c * KVPAD + tc * 4 + j];
#pragma unroll
            for (int i = 0; i < 4; i++)
#pragma unroll
                for (int j = 0; j < 4; j++)
                    acc2[i][j] += pr[i] * vr[j];
        }
    }

#pragma unroll
    for (int i = 0; i < 4; i++) {
        int r = tr * 4 + i;
        float inv = 1.0f / sSum[r];
#pragma unroll
        for (int j = 0; j < 4; j++) {
            O[(size_t)(rowbase + q0 + r) * DMODEL + colbase + tc * 4 + j] = acc2[i][j] * inv;
        }
    }
}

// ---------------- launcher ----------------
extern "C" void kernel_launch(void* const* d_in, const int* in_sizes, int n_in,
                              void* d_out, int out_size)
{
    const float* hid = (const float*)d_in[0];
    const float* Wq  = (const float*)d_in[1];
    const float* bq  = (const float*)d_in[2];
    const float* Wk  = (const float*)d_in[3];
    const float* bk  = (const float*)d_in[4];
    const float* Wv  = (const float*)d_in[5];
    const float* bv  = (const float*)d_in[6];
    const float* Wo  = (const float*)d_in[7];
    const float* bo  = (const float*)d_in[8];
    float* out = (float*)d_out;

    float *q, *k, *v, *ctx;
    __nv_bfloat16 *qkh, *qkl, *hih, *hil, *cth, *ctl;
    __nv_bfloat16 *wqh, *wql, *wkh, *wkl, *wvh, *wvl, *woh, *wol;
    cudaGetSymbolAddress((void**)&q,   g_q);
    cudaGetSymbolAddress((void**)&k,   g_k);
    cudaGetSymbolAddress((void**)&v,   g_v);
    cudaGetSymbolAddress((void**)&ctx, g_ctx);
    cudaGetSymbolAddress((void**)&qkh, g_qk_h);
    cudaGetSymbolAddress((void**)&qkl, g_qk_l);
    cudaGetSymbolAddress((void**)&hih, g_hid_h);
    cudaGetSymbolAddress((void**)&hil, g_hid_l);
    cudaGetSymbolAddress((void**)&cth, g_ctx_h);
    cudaGetSymbolAddress((void**)&ctl, g_ctx_l);
    cudaGetSymbolAddress((void**)&wqh, g_wq_h);
    cudaGetSymbolAddress((void**)&wql, g_wq_l);
    cudaGetSymbolAddress((void**)&wkh, g_wk_h);
    cudaGetSymbolAddress((void**)&wkl, g_wk_l);
    cudaGetSymbolAddress((void**)&wvh, g_wv_h);
    cudaGetSymbolAddress((void**)&wvl, g_wv_l);
    cudaGetSymbolAddress((void**)&woh, g_wo_h);
    cudaGetSymbolAddress((void**)&wol, g_wo_l);

    cudaFuncSetAttribute(gemm_mma, cudaFuncAttributeMaxDynamicSharedMemorySize, GEMM_SMEM);

    // 1. RoPE + split (Q/K GEMM input)
    {
        int NP = MROWS * DMODEL / 2;
        rope_split_kernel<<<(NP + 255) / 256, 256>>>(hid, qkh, qkl);
    }
    // 2. split raw hidden (V GEMM input)
    split_kernel<<<(MROWS * DMODEL + 255) / 256, 256>>>(hid, hih, hil);
    // 3. weight transpose + split
    {
        dim3 g(DMODEL / 32, DMODEL / 32), b(32, 8);
        wtrans_split<<<g, b>>>(Wq, wqh, wql);
        wtrans_split<<<g, b>>>(Wk, wkh, wkl);
        wtrans_split<<<g, b>>>(Wv, wvh, wvl);
        wtrans_split<<<g, b>>>(Wo, woh, wol);
    }
    // 4. Q/K/V projections (fused, gridDim.z = 3)
    {
        GemmArgs a;
        a.Ah[0] = qkh; a.Al[0] = qkl; a.Bh[0] = wqh; a.Bl[0] = wql; a.bias[0] = bq; a.C[0] = q;
        a.Ah[1] = qkh; a.Al[1] = qkl; a.Bh[1] = wkh; a.Bl[1] = wkl; a.bias[1] = bk; a.C[1] = k;
        a.Ah[2] = hih; a.Al[2] = hil; a.Bh[2] = wvh; a.Bl[2] = wvl; a.bias[2] = bv; a.C[2] = v;
        dim3 grid(DMODEL / GBN, MROWS / GBM, 3);   // (6, 32, 3)
        gemm_mma<<<grid, 256, GEMM_SMEM>>>(a);
    }
    // 5. attention
    {
        int smem = (BQ * DH + KT * KVPAD + BQ * SSTR + BQ) * (int)sizeof(float);
        cudaFuncSetAttribute(attn_kernel, cudaFuncAttributeMaxDynamicSharedMemorySize, smem);
        dim3 grid(SEQ / BQ, HEADS, BATCH);
        attn_kernel<<<grid, 256, smem>>>(q, k, v, ctx);
    }
    // 6. split ctx, output projection
    split_kernel<<<(MROWS * DMODEL + 255) / 256, 256>>>(ctx, cth, ctl);
    {
        GemmArgs a;
        a.Ah[0] = cth; a.Al[0] = ctl; a.Bh[0] = woh; a.Bl[0] = wol; a.bias[0] = bo; a.C[0] = out;
        dim3 grid(DMODEL / GBN, MROWS / GBM, 1);
        gemm_mma<<<grid, 256, GEMM_SMEM>>>(a);
    }
}

// round 5
// speedup vs baseline: 3.3075x; 1.5060x over previous
#include <cuda_runtime.h>
#include <cuda_bf16.h>
#include <math.h>
#include <stdint.h>

#define BATCH   2
#define SEQ     2048
#define HEADS   12
#define DH      64
#define DMODEL  768
#define MROWS   (BATCH * SEQ)    // 4096
#define WIN     128

// ---------------- scratch (__device__ globals; no allocation allowed) ----------------
__device__ __align__(256) __nv_bfloat16 g_qk_h[MROWS * DMODEL];
__device__ __align__(256) __nv_bfloat16 g_qk_l[MROWS * DMODEL];
__device__ __align__(256) __nv_bfloat16 g_hid_h[MROWS * DMODEL];
__device__ __align__(256) __nv_bfloat16 g_hid_l[MROWS * DMODEL];
__device__ __align__(256) __nv_bfloat16 g_q_h[MROWS * DMODEL];
__device__ __align__(256) __nv_bfloat16 g_q_l[MROWS * DMODEL];
__device__ __align__(256) __nv_bfloat16 g_k_h[MROWS * DMODEL];
__device__ __align__(256) __nv_bfloat16 g_k_l[MROWS * DMODEL];
__device__ __align__(256) __nv_bfloat16 g_v_h[MROWS * DMODEL];
__device__ __align__(256) __nv_bfloat16 g_v_l[MROWS * DMODEL];
__device__ __align__(256) __nv_bfloat16 g_ctx_h[MROWS * DMODEL];
__device__ __align__(256) __nv_bfloat16 g_ctx_l[MROWS * DMODEL];
__device__ __align__(256) __nv_bfloat16 g_wq_h[DMODEL * DMODEL];
__device__ __align__(256) __nv_bfloat16 g_wq_l[DMODEL * DMODEL];
__device__ __align__(256) __nv_bfloat16 g_wk_h[DMODEL * DMODEL];
__device__ __align__(256) __nv_bfloat16 g_wk_l[DMODEL * DMODEL];
__device__ __align__(256) __nv_bfloat16 g_wv_h[DMODEL * DMODEL];
__device__ __align__(256) __nv_bfloat16 g_wv_l[DMODEL * DMODEL];
__device__ __align__(256) __nv_bfloat16 g_wo_h[DMODEL * DMODEL];
__device__ __align__(256) __nv_bfloat16 g_wo_l[DMODEL * DMODEL];

// ---------------- PTX helpers ----------------
__device__ __forceinline__ uint32_t smem_u32(const void* p) {
    uint32_t a;
    asm("{ .reg .u64 t; cvta.to.shared.u64 t, %1; cvt.u32.u64 %0, t; }" : "=r"(a) : "l"(p));
    return a;
}
__device__ __forceinline__ void cpa16(uint32_t dst, const void* src) {
    asm volatile("cp.async.cg.shared.global [%0], [%1], 16;" :: "r"(dst), "l"(src));
}
// predicated: valid (clamped) address always; src-size 0 zero-fills when !ok
__device__ __forceinline__ void cpa16p(uint32_t dst, const void* src, bool ok) {
    int sz = ok ? 16 : 0;
    asm volatile("cp.async.cg.shared.global [%0], [%1], 16, %2;" :: "r"(dst), "l"(src), "r"(sz));
}
#define CP_COMMIT() asm volatile("cp.async.commit_group;")
#define CP_WAIT(N)  asm volatile("cp.async.wait_group %0;" :: "n"(N))

__device__ __forceinline__ void ldsm4(uint32_t& r0, uint32_t& r1, uint32_t& r2, uint32_t& r3,
                                      uint32_t addr) {
    asm volatile("ldmatrix.sync.aligned.m8n8.x4.shared.b16 {%0,%1,%2,%3}, [%4];"
                 : "=r"(r0), "=r"(r1), "=r"(r2), "=r"(r3) : "r"(addr));
}
__device__ __forceinline__ void ldsm4t(uint32_t& r0, uint32_t& r1, uint32_t& r2, uint32_t& r3,
                                       uint32_t addr) {
    asm volatile("ldmatrix.sync.aligned.m8n8.x4.trans.shared.b16 {%0,%1,%2,%3}, [%4];"
                 : "=r"(r0), "=r"(r1), "=r"(r2), "=r"(r3) : "r"(addr));
}
__device__ __forceinline__ void mma16816(float* d, const uint32_t* a, uint32_t b0, uint32_t b1) {
    asm volatile(
        "mma.sync.aligned.m16n8k16.row.col.f32.bf16.bf16.f32 "
        "{%0,%1,%2,%3}, {%4,%5,%6,%7}, {%8,%9}, {%0,%1,%2,%3};"
        : "+f"(d[0]), "+f"(d[1]), "+f"(d[2]), "+f"(d[3])
        : "r"(a[0]), "r"(a[1]), "r"(a[2]), "r"(a[3]), "r"(b0), "r"(b1));
}

__device__ __forceinline__ void split_one(float x, __nv_bfloat16& h, __nv_bfloat16& l) {
    h = __float2bfloat16(x);
    l = __float2bfloat16(x - __bfloat162float(h));
}
__device__ __forceinline__ void split_pack(float a, float b, uint32_t& H, uint32_t& L) {
    __nv_bfloat16 ah = __float2bfloat16(a), bh = __float2bfloat16(b);
    float ar = a - __bfloat162float(ah), br = b - __bfloat162float(bh);
    __nv_bfloat162 hh; hh.x = ah; hh.y = bh;
    __nv_bfloat162 ll; ll.x = __float2bfloat16(ar); ll.y = __float2bfloat16(br);
    H = *(uint32_t*)&hh;
    L = *(uint32_t*)&ll;
}

// ---------------- prep: RoPE + split rope'd AND raw hidden in one pass ----------------
__global__ void prep_kernel(const float* __restrict__ x,
                            __nv_bfloat16* __restrict__ qh, __nv_bfloat16* __restrict__ ql,
                            __nv_bfloat16* __restrict__ hh, __nv_bfloat16* __restrict__ hl) {
    const int NP = MROWS * DMODEL / 2;
    int idx = blockIdx.x * blockDim.x + threadIdx.x;
    if (idx >= NP) return;
    int row = idx / (DMODEL / 2);
    int rem = idx % (DMODEL / 2);
    int h = rem / 32;
    int i = rem % 32;
    int s = row % SEQ;
    // 10000^(-i/32) = exp2(-i/32 * log2(10000))
    float inv = exp2f(-(float)i * (0.03125f * 13.28771238f));
    float sn, cs;
    sincosf((float)s * inv, &sn, &cs);
    int base = row * DMODEL + h * DH;
    float x1 = x[base + i];
    float x2 = x[base + 32 + i];
    float y1 = x1 * cs - x2 * sn;
    float y2 = x2 * cs + x1 * sn;
    __nv_bfloat16 a, b;
    split_one(y1, a, b); qh[base + i] = a;      ql[base + i] = b;
    split_one(y2, a, b); qh[base + 32 + i] = a; ql[base + 32 + i] = b;
    split_one(x1, a, b); hh[base + i] = a;      hl[base + i] = b;
    split_one(x2, a, b); hh[base + 32 + i] = a; hl[base + 32 + i] = b;
}

// ---------------- fused weight transpose + split (z selects matrix) ----------------
struct WArgs {
    const float* W[4];
    __nv_bfloat16* oh[4];
    __nv_bfloat16* ol[4];
};
__global__ void wtrans_split4(WArgs args) {
    __shared__ float t[32][33];
    int z = blockIdx.z;
    const float* W = args.W[z];
    __nv_bfloat16* oh = args.oh[z];
    __nv_bfloat16* ol = args.ol[z];
    int nb = blockIdx.x * 32, kb = blockIdx.y * 32;
    int tx = threadIdx.x, ty = threadIdx.y;   // (32, 8)
#pragma unroll
    for (int r = 0; r < 32; r += 8)
        t[ty + r][tx] = W[(size_t)(kb + ty + r) * DMODEL + nb + tx];
    __syncthreads();
#pragma unroll
    for (int r = 0; r < 32; r += 8) {
        float x = t[tx][ty + r];
        __nv_bfloat16 h, l;
        split_one(x, h, l);
        size_t o = (size_t)(nb + ty + r) * DMODEL + kb + tx;
        oh[o] = h; ol[o] = l;
    }
}

// ---------------- mma.sync bf16x3 GEMM: 128x128 tile, BK=64, 8 warps ----------------
#define GBM 128
#define GBN 128
#define GK  768
#define NCH (GK / 64)            // 12
#define MAT_BYTES (128 * 128)
#define STAGE_BYTES (4 * MAT_BYTES)
#define GEMM_SMEM (2 * STAGE_BYTES)   // 131072

struct GemmArgs {
    const __nv_bfloat16* Ah[3];
    const __nv_bfloat16* Al[3];
    const __nv_bfloat16* Bh[3];
    const __nv_bfloat16* Bl[3];
    const float* bias[3];
    float* Cf[3];                 // fp32 output (if non-null)
    __nv_bfloat16* Ch[3];         // else bf16 split outputs
    __nv_bfloat16* Cl[3];
    float scale[3];
};

__device__ __forceinline__ void load_chunk(
    uint32_t st,
    const __nv_bfloat16* __restrict__ Ah, const __nv_bfloat16* __restrict__ Al,
    const __nv_bfloat16* __restrict__ Bh, const __nv_bfloat16* __restrict__ Bl,
    int m0, int n0, int kc, int tid)
{
    int k0 = kc * 64;
#pragma unroll
    for (int i = 0; i < 4; i++) {
        int u = tid + i * 256;
        int r = u >> 3, c = u & 7;
        uint32_t off = (uint32_t)(r * 128) + (uint32_t)((c ^ (r & 7)) << 4);
        size_t ga = (size_t)(m0 + r) * GK + k0 + c * 8;
        size_t gb = (size_t)(n0 + r) * GK + k0 + c * 8;
        cpa16(st + off,                 Ah + ga);
        cpa16(st + MAT_BYTES + off,     Al + ga);
        cpa16(st + 2 * MAT_BYTES + off, Bh + gb);
        cpa16(st + 3 * MAT_BYTES + off, Bl + gb);
    }
}

__global__ __launch_bounds__(256, 1) void gemm_mma(GemmArgs args)
{
    extern __shared__ __align__(1024) char sm[];
    uint32_t sb = smem_u32(sm);
    int tid = threadIdx.x, lane = tid & 31, warp = tid >> 5;
    int wm = warp >> 1, wn = warp & 1;
    int z = blockIdx.z;
    int m0 = blockIdx.y * GBM, n0 = blockIdx.x * GBN;

    const __nv_bfloat16* Ah = args.Ah[z];
    const __nv_bfloat16* Al = args.Al[z];
    const __nv_bfloat16* Bh = args.Bh[z];
    const __nv_bfloat16* Bl = args.Bl[z];
    const float* bias = args.bias[z];

    float acc[2][8][4];
#pragma unroll
    for (int a = 0; a < 2; a++)
#pragma unroll
        for (int b = 0; b < 8; b++)
#pragma unroll
            for (int c = 0; c < 4; c++) acc[a][b][c] = 0.f;

    load_chunk(sb, Ah, Al, Bh, Bl, m0, n0, 0, tid);
    CP_COMMIT();

    for (int kc = 0; kc < NCH; kc++) {
        if (kc + 1 < NCH) {
            load_chunk(sb + ((kc + 1) & 1) * STAGE_BYTES, Ah, Al, Bh, Bl, m0, n0, kc + 1, tid);
            CP_COMMIT();
            CP_WAIT(1);
        } else {
            CP_WAIT(0);
        }
        __syncthreads();

        uint32_t base = sb + (kc & 1) * STAGE_BYTES;
#pragma unroll
        for (int ks = 0; ks < 4; ks++) {
            int c0 = ks * 2;
            uint32_t ah[2][4], al[2][4];
#pragma unroll
            for (int mt = 0; mt < 2; mt++) {
                int row = wm * 32 + mt * 16 + (lane & 15);
                int ch = c0 + (lane >> 4);
                uint32_t off = (uint32_t)(row * 128) + (uint32_t)(((ch ^ (row & 7))) << 4);
                ldsm4(ah[mt][0], ah[mt][1], ah[mt][2], ah[mt][3], base + off);
                ldsm4(al[mt][0], al[mt][1], al[mt][2], al[mt][3], base + MAT_BYTES + off);
            }
            uint32_t bh[4][4], bl[4][4];
#pragma unroll
            for (int p = 0; p < 4; p++) {
                int row = wn * 64 + p * 16 + (lane & 7) + ((lane >> 4) << 3);
                int ch = c0 + ((lane >> 3) & 1);
                uint32_t off = (uint32_t)(row * 128) + (uint32_t)(((ch ^ (row & 7))) << 4);
                ldsm4(bh[p][0], bh[p][1], bh[p][2], bh[p][3], base + 2 * MAT_BYTES + off);
                ldsm4(bl[p][0], bl[p][1], bl[p][2], bl[p][3], base + 3 * MAT_BYTES + off);
            }
#pragma unroll
            for (int mt = 0; mt < 2; mt++) {
#pragma unroll
                for (int p = 0; p < 4; p++) {
                    mma16816(acc[mt][2 * p],     ah[mt], bh[p][0], bh[p][1]);
                    mma16816(acc[mt][2 * p],     al[mt], bh[p][0], bh[p][1]);
                    mma16816(acc[mt][2 * p],     ah[mt], bl[p][0], bl[p][1]);
                    mma16816(acc[mt][2 * p + 1], ah[mt], bh[p][2], bh[p][3]);
                    mma16816(acc[mt][2 * p + 1], al[mt], bh[p][2], bh[p][3]);
                    mma16816(acc[mt][2 * p + 1], ah[mt], bl[p][2], bl[p][3]);
                }
            }
        }
        __syncthreads();
    }

    float scale = args.scale[z];
    float* Cf = args.Cf[z];
    if (Cf) {
#pragma unroll
        for (int mt = 0; mt < 2; mt++) {
            int row = m0 + wm * 32 + mt * 16 + (lane >> 2);
#pragma unroll
            for (int nt = 0; nt < 8; nt++) {
                int col = n0 + wn * 64 + nt * 8 + 2 * (lane & 3);
                float b0 = bias[col], b1 = bias[col + 1];
                float2 v0 = make_float2((acc[mt][nt][0] + b0) * scale, (acc[mt][nt][1] + b1) * scale);
                float2 v1 = make_float2((acc[mt][nt][2] + b0) * scale, (acc[mt][nt][3] + b1) * scale);
                *(float2*)(Cf + (size_t)row * DMODEL + col) = v0;
                *(float2*)(Cf + (size_t)(row + 8) * DMODEL + col) = v1;
            }
        }
    } else {
        __nv_bfloat16* Ch = args.Ch[z];
        __nv_bfloat16* Cl = args.Cl[z];
#pragma unroll
        for (int mt = 0; mt < 2; mt++) {
            int row = m0 + wm * 32 + mt * 16 + (lane >> 2);
#pragma unroll
            for (int nt = 0; nt < 8; nt++) {
                int col = n0 + wn * 64 + nt * 8 + 2 * (lane & 3);
                float b0 = bias[col], b1 = bias[col + 1];
                uint32_t H, L;
                split_pack((acc[mt][nt][0] + b0) * scale, (acc[mt][nt][1] + b1) * scale, H, L);
                *(uint32_t*)(Ch + (size_t)row * DMODEL + col) = H;
                *(uint32_t*)(Cl + (size_t)row * DMODEL + col) = L;
                split_pack((acc[mt][nt][2] + b0) * scale, (acc[mt][nt][3] + b1) * scale, H, L);
                *(uint32_t*)(Ch + (size_t)(row + 8) * DMODEL + col) = H;
                *(uint32_t*)(Cl + (size_t)(row + 8) * DMODEL + col) = L;
            }
        }
    }
}

// ---------------- tensor-core flash attention ----------------
#define ATT_SMEM (16384 + 2 * 32768)

__device__ __forceinline__ void attn_load_kv(
    uint32_t st,
    const __nv_bfloat16* __restrict__ Kh_, const __nv_bfloat16* __restrict__ Kl_,
    const __nv_bfloat16* __restrict__ Vh_, const __nv_bfloat16* __restrict__ Vl_,
    int rowbase, int colbase, int kstart, int kt, int tid)
{
#pragma unroll
    for (int it = 0; it < 4; it++) {
        int u = tid + it * 128;
        int r = u >> 3, c = u & 7;
        int j = kstart + kt * 64 + r;
        bool ok = ((unsigned)j < (unsigned)SEQ);
        int jj = ok ? j : 0;
        uint32_t off = (uint32_t)(r * 128) + (uint32_t)((c ^ (r & 7)) << 4);
        size_t go = (size_t)(rowbase + jj) * DMODEL + colbase + c * 8;
        cpa16p(st + off,         Kh_ + go, ok);
        cpa16p(st + 8192 + off,  Kl_ + go, ok);
        cpa16p(st + 16384 + off, Vh_ + go, ok);
        cpa16p(st + 24576 + off, Vl_ + go, ok);
    }
}

__global__ __launch_bounds__(128, 1) void attn_mma(
    const __nv_bfloat16* __restrict__ Qh_, const __nv_bfloat16* __restrict__ Ql_,
    const __nv_bfloat16* __restrict__ Kh_, const __nv_bfloat16* __restrict__ Kl_,
    const __nv_bfloat16* __restrict__ Vh_, const __nv_bfloat16* __restrict__ Vl_,
    __nv_bfloat16* __restrict__ Ch_, __nv_bfloat16* __restrict__ Cl_)
{
    extern __shared__ __align__(1024) char sm[];
    uint32_t sb = smem_u32(sm);
    int tid = threadIdx.x, lane = tid & 31, wrp = tid >> 5;
    int q0 = blockIdx.x * 64;
    int rowbase = blockIdx.z * SEQ;
    int colbase = blockIdx.y * DH;
    int kstart = q0 - WIN;

#pragma unroll
    for (int it = 0; it < 4; it++) {
        int u = tid + it * 128;
        int r = u >> 3, c = u & 7;
        uint32_t off = (uint32_t)(r * 128) + (uint32_t)((c ^ (r & 7)) << 4);
        size_t go = (size_t)(rowbase + q0 + r) * DMODEL + colbase + c * 8;
        cpa16(sb + off, Qh_ + go);
        cpa16(sb + 8192 + off, Ql_ + go);
    }
    attn_load_kv(sb + 16384, Kh_, Kl_, Vh_, Vl_, rowbase, colbase, kstart, 0, tid);
    CP_COMMIT();

    float oacc[8][4];
#pragma unroll
    for (int a = 0; a < 8; a++)
#pragma unroll
        for (int b = 0; b < 4; b++) oacc[a][b] = 0.f;
    float l0 = 0.f, l1 = 0.f, m0p = -1e30f, m1p = -1e30f;
    uint32_t qfh[4][4], qfl[4][4];

    for (int kt = 0; kt < 5; kt++) {
        if (kt < 4) {
            attn_load_kv(sb + 16384 + ((kt + 1) & 1) * 32768,
                         Kh_, Kl_, Vh_, Vl_, rowbase, colbase, kstart, kt + 1, tid);
            CP_COMMIT();
            CP_WAIT(1);
        } else {
            CP_WAIT(0);
        }
        __syncthreads();

        if (kt == 0) {
#pragma unroll
            for (int ks = 0; ks < 4; ks++) {
                int row = wrp * 16 + (lane & 15);
                int ch = ks * 2 + (lane >> 4);
                uint32_t off = (uint32_t)(row * 128) + (uint32_t)(((ch ^ (row & 7))) << 4);
                ldsm4(qfh[ks][0], qfh[ks][1], qfh[ks][2], qfh[ks][3], sb + off);
                ldsm4(qfl[ks][0], qfl[ks][1], qfl[ks][2], qfl[ks][3], sb + 8192 + off);
            }
        }

        uint32_t st = sb + 16384 + (kt & 1) * 32768;

        // ---- scores: S = Qh Kh^T + Ql Kh^T + Qh Kl^T ----
        float sacc[8][4];
#pragma unroll
        for (int a = 0; a < 8; a++)
#pragma unroll
            for (int b = 0; b < 4; b++) sacc[a][b] = 0.f;
#pragma unroll
        for (int ks = 0; ks < 4; ks++) {
#pragma unroll
            for (int p = 0; p < 4; p++) {
                int row = p * 16 + (lane & 7) + ((lane >> 4) << 3);
                int ch = ks * 2 + ((lane >> 3) & 1);
                uint32_t off = (uint32_t)(row * 128) + (uint32_t)(((ch ^ (row & 7))) << 4);
                uint32_t kh0, kh1, kh2, kh3, kl0, kl1, kl2, kl3;
                ldsm4(kh0, kh1, kh2, kh3, st + off);
                ldsm4(kl0, kl1, kl2, kl3, st + 8192 + off);
                mma16816(sacc[2 * p],     qfh[ks], kh0, kh1);
                mma16816(sacc[2 * p],     qfl[ks], kh0, kh1);
                mma16816(sacc[2 * p],     qfh[ks], kl0, kl1);
                mma16816(sacc[2 * p + 1], qfh[ks], kh2, kh3);
                mma16816(sacc[2 * p + 1], qfl[ks], kh2, kh3);
                mma16816(sacc[2 * p + 1], qfh[ks], kl2, kl3);
            }
        }

        // ---- mask + online softmax ----
        int i0 = q0 + wrp * 16 + (lane >> 2);
        int i1 = i0 + 8;
        float mt0 = -1e30f, mt1 = -1e30f;
#pragma unroll
        for (int nt = 0; nt < 8; nt++) {
            int j0 = kstart + kt * 64 + nt * 8 + 2 * (lane & 3);
            int j1 = j0 + 1;
            bool u0 = ((unsigned)j0 < (unsigned)SEQ);
            bool u1 = ((unsigned)j1 < (unsigned)SEQ);
            bool v00 = u0 && (j0 > i0 - WIN) && (j0 < i0 + WIN);
            bool v01 = u1 && (j1 > i0 - WIN) && (j1 < i0 + WIN);
            bool v10 = u0 && (j0 > i1 - WIN) && (j0 < i1 + WIN);
            bool v11 = u1 && (j1 > i1 - WIN) && (j1 < i1 + WIN);
            sacc[nt][0] = v00 ? sacc[nt][0] : -1e30f;
            sacc[nt][1] = v01 ? sacc[nt][1] : -1e30f;
            sacc[nt][2] = v10 ? sacc[nt][2] : -1e30f;
            sacc[nt][3] = v11 ? sacc[nt][3] : -1e30f;
            mt0 = fmaxf(mt0, fmaxf(sacc[nt][0], sacc[nt][1]));
            mt1 = fmaxf(mt1, fmaxf(sacc[nt][2], sacc[nt][3]));
        }
        mt0 = fmaxf(mt0, __shfl_xor_sync(0xffffffffu, mt0, 1));
        mt0 = fmaxf(mt0, __shfl_xor_sync(0xffffffffu, mt0, 2));
        mt1 = fmaxf(mt1, __shfl_xor_sync(0xffffffffu, mt1, 1));
        mt1 = fmaxf(mt1, __shfl_xor_sync(0xffffffffu, mt1, 2));
        float mn0 = fmaxf(m0p, mt0), mn1 = fmaxf(m1p, mt1);
        float f0 = __expf(m0p - mn0), f1 = __expf(m1p - mn1);
        m0p = mn0; m1p = mn1;
        l0 *= f0; l1 *= f1;
#pragma unroll
        for (int nt = 0; nt < 8; nt++) {
            oacc[nt][0] *= f0; oacc[nt][1] *= f0;
            oacc[nt][2] *= f1; oacc[nt][3] *= f1;
        }

        // ---- P = exp(s - m) -> A fragments (hi/lo) ----
        uint32_t pa[4][4], pla[4][4];
#pragma unroll
        for (int s2 = 0; s2 < 4; s2++) {
            int nt0 = 2 * s2, nt1 = nt0 + 1;
            float p00 = __expf(sacc[nt0][0] - mn0), p01 = __expf(sacc[nt0][1] - mn0);
            float p02 = __expf(sacc[nt0][2] - mn1), p03 = __expf(sacc[nt0][3] - mn1);
            float p10 = __expf(sacc[nt1][0] - mn0), p11 = __expf(sacc[nt1][1] - mn0);
            float p12 = __expf(sacc[nt1][2] - mn1), p13 = __expf(sacc[nt1][3] - mn1);
            l0 += p00 + p01 + p10 + p11;
            l1 += p02 + p03 + p12 + p13;
            split_pack(p00, p01, pa[s2][0], pla[s2][0]);
            split_pack(p02, p03, pa[s2][1], pla[s2][1]);
            split_pack(p10, p11, pa[s2][2], pla[s2][2]);
            split_pack(p12, p13, pa[s2][3], pla[s2][3]);
        }

        // ---- O += Ph Vh + Pl Vh + Ph Vl ----
#pragma unroll
        for (int s2 = 0; s2 < 4; s2++) {
#pragma unroll
            for (int c = 0; c < 4; c++) {
                int row = s2 * 16 + (lane & 7) + (((lane >> 3) & 1) << 3);
                int ch = 2 * c + (lane >> 4);
                uint32_t off = (uint32_t)(row * 128) + (uint32_t)(((ch ^ (row & 7))) << 4);
                uint32_t vh0, vh1, vh2, vh3, vl0, vl1, vl2, vl3;
                ldsm4t(vh0, vh1, vh2, vh3, st + 16384 + off);
                ldsm4t(vl0, vl1, vl2, vl3, st + 24576 + off);
                mma16816(oacc[2 * c],     pa[s2],  vh0, vh1);
                mma16816(oacc[2 * c],     pla[s2], vh0, vh1);
                mma16816(oacc[2 * c],     pa[s2],  vl0, vl1);
                mma16816(oacc[2 * c + 1], pa[s2],  vh2, vh3);
                mma16816(oacc[2 * c + 1], pla[s2], vh2, vh3);
                mma16816(oacc[2 * c + 1], pa[s2],  vl2, vl3);
            }
        }
        __syncthreads();
    }

    l0 += __shfl_xor_sync(0xffffffffu, l0, 1);
    l0 += __shfl_xor_sync(0xffffffffu, l0, 2);
    l1 += __shfl_xor_sync(0xffffffffu, l1, 1);
    l1 += __shfl_xor_sync(0xffffffffu, l1, 2);
    float inv0 = 1.0f / l0, inv1 = 1.0f / l1;
    int r0 = rowbase + q0 + wrp * 16 + (lane >> 2);
#pragma unroll
    for (int nt = 0; nt < 8; nt++) {
        int col = colbase + nt * 8 + 2 * (lane & 3);
        uint32_t H, L;
        split_pack(oacc[nt][0] * inv0, oacc[nt][1] * inv0, H, L);
        *(uint32_t*)(Ch_ + (size_t)r0 * DMODEL + col) = H;
        *(uint32_t*)(Cl_ + (size_t)r0 * DMODEL + col) = L;
        split_pack(oacc[nt][2] * inv1, oacc[nt][3] * inv1, H, L);
        *(uint32_t*)(Ch_ + (size_t)(r0 + 8) * DMODEL + col) = H;
        *(uint32_t*)(Cl_ + (size_t)(r0 + 8) * DMODEL + col) = L;
    }
}

// ---------------- launcher ----------------
extern "C" void kernel_launch(void* const* d_in, const int* in_sizes, int n_in,
                              void* d_out, int out_size)
{
    const float* hid = (const float*)d_in[0];
    const float* Wq  = (const float*)d_in[1];
    const float* bq  = (const float*)d_in[2];
    const float* Wk  = (const float*)d_in[3];
    const float* bk  = (const float*)d_in[4];
    const float* Wv  = (const float*)d_in[5];
    const float* bv  = (const float*)d_in[6];
    const float* Wo  = (const float*)d_in[7];
    const float* bo  = (const float*)d_in[8];
    float* out = (float*)d_out;

    __nv_bfloat16 *qkh, *qkl, *hih, *hil, *cth, *ctl;
    __nv_bfloat16 *qh, *ql, *kh, *kl, *vh, *vl;
    __nv_bfloat16 *wqh, *wql, *wkh, *wkl, *wvh, *wvl, *woh, *wol;
    cudaGetSymbolAddress((void**)&qkh, g_qk_h);
    cudaGetSymbolAddress((void**)&qkl, g_qk_l);
    cudaGetSymbolAddress((void**)&hih, g_hid_h);
    cudaGetSymbolAddress((void**)&hil, g_hid_l);
    cudaGetSymbolAddress((void**)&cth, g_ctx_h);
    cudaGetSymbolAddress((void**)&ctl, g_ctx_l);
    cudaGetSymbolAddress((void**)&qh,  g_q_h);
    cudaGetSymbolAddress((void**)&ql,  g_q_l);
    cudaGetSymbolAddress((void**)&kh,  g_k_h);
    cudaGetSymbolAddress((void**)&kl,  g_k_l);
    cudaGetSymbolAddress((void**)&vh,  g_v_h);
    cudaGetSymbolAddress((void**)&vl,  g_v_l);
    cudaGetSymbolAddress((void**)&wqh, g_wq_h);
    cudaGetSymbolAddress((void**)&wql, g_wq_l);
    cudaGetSymbolAddress((void**)&wkh, g_wk_h);
    cudaGetSymbolAddress((void**)&wkl, g_wk_l);
    cudaGetSymbolAddress((void**)&wvh, g_wv_h);
    cudaGetSymbolAddress((void**)&wvl, g_wv_l);
    cudaGetSymbolAddress((void**)&woh, g_wo_h);
    cudaGetSymbolAddress((void**)&wol, g_wo_l);

    cudaFuncSetAttribute(gemm_mma, cudaFuncAttributeMaxDynamicSharedMemorySize, GEMM_SMEM);
    cudaFuncSetAttribute(attn_mma, cudaFuncAttributeMaxDynamicSharedMemorySize, ATT_SMEM);

    {
        int NP = MROWS * DMODEL / 2;
        prep_kernel<<<(NP + 255) / 256, 256>>>(hid, qkh, qkl, hih, hil);
    }
    {
        WArgs wa;
        wa.W[0] = Wq; wa.oh[0] = wqh; wa.ol[0] = wql;
        wa.W[1] = Wk; wa.oh[1] = wkh; wa.ol[1] = wkl;
        wa.W[2] = Wv; wa.oh[2] = wvh; wa.ol[2] = wvl;
        wa.W[3] = Wo; wa.oh[3] = woh; wa.ol[3] = wol;
        dim3 g(DMODEL / 32, DMODEL / 32, 4), b(32, 8);
        wtrans_split4<<<g, b>>>(wa);
    }
    {
        GemmArgs a = {};
        a.Ah[0] = qkh; a.Al[0] = qkl; a.Bh[0] = wqh; a.Bl[0] = wql; a.bias[0] = bq;
        a.Cf[0] = nullptr; a.Ch[0] = qh; a.Cl[0] = ql; a.scale[0] = 0.125f;
        a.Ah[1] = qkh; a.Al[1] = qkl; a.Bh[1] = wkh; a.Bl[1] = wkl; a.bias[1] = bk;
        a.Cf[1] = nullptr; a.Ch[1] = kh; a.Cl[1] = kl; a.scale[1] = 1.0f;
        a.Ah[2] = hih; a.Al[2] = hil; a.Bh[2] = wvh; a.Bl[2] = wvl; a.bias[2] = bv;
        a.Cf[2] = nullptr; a.Ch[2] = vh; a.Cl[2] = vl; a.scale[2] = 1.0f;
        dim3 grid(DMODEL / GBN, MROWS / GBM, 3);
        gemm_mma<<<grid, 256, GEMM_SMEM>>>(a);
    }
    {
        dim3 grid(SEQ / 64, HEADS, BATCH);
        attn_mma<<<grid, 128, ATT_SMEM>>>(qh, ql, kh, kl, vh, vl, cth, ctl);
    }
    {
        GemmArgs a = {};
        a.Ah[0] = cth; a.Al[0] = ctl; a.Bh[0] = woh; a.Bl[0] = wol; a.bias[0] = bo;
        a.Cf[0] = out; a.scale[0] = 1.0f;
        dim3 grid(DMODEL / GBN, MROWS / GBM, 1);
        gemm_mma<<<grid, 256, GEMM_SMEM>>>(a);
    }
}

// round 6
// speedup vs baseline: 3.4711x; 1.0495x over previous
#include <cuda_runtime.h>
#include <cuda_bf16.h>
#include <math.h>
#include <stdint.h>

#define BATCH   2
#define SEQ     2048
#define HEADS   12
#define DH      64
#define DMODEL  768
#define MROWS   (BATCH * SEQ)    // 4096
#define WIN     128

// ---------------- scratch (__device__ globals; no allocation allowed) ----------------
__device__ __align__(256) __nv_bfloat16 g_qk_h[MROWS * DMODEL];
__device__ __align__(256) __nv_bfloat16 g_qk_l[MROWS * DMODEL];
__device__ __align__(256) __nv_bfloat16 g_hid_h[MROWS * DMODEL];
__device__ __align__(256) __nv_bfloat16 g_hid_l[MROWS * DMODEL];
__device__ __align__(256) __nv_bfloat16 g_q_h[MROWS * DMODEL];
__device__ __align__(256) __nv_bfloat16 g_q_l[MROWS * DMODEL];
__device__ __align__(256) __nv_bfloat16 g_k_h[MROWS * DMODEL];
__device__ __align__(256) __nv_bfloat16 g_k_l[MROWS * DMODEL];
__device__ __align__(256) __nv_bfloat16 g_v_h[MROWS * DMODEL];
__device__ __align__(256) __nv_bfloat16 g_v_l[MROWS * DMODEL];
__device__ __align__(256) __nv_bfloat16 g_ctx_h[MROWS * DMODEL];
__device__ __align__(256) __nv_bfloat16 g_ctx_l[MROWS * DMODEL];
__device__ __align__(256) __nv_bfloat16 g_wq_h[DMODEL * DMODEL];
__device__ __align__(256) __nv_bfloat16 g_wq_l[DMODEL * DMODEL];
__device__ __align__(256) __nv_bfloat16 g_wk_h[DMODEL * DMODEL];
__device__ __align__(256) __nv_bfloat16 g_wk_l[DMODEL * DMODEL];
__device__ __align__(256) __nv_bfloat16 g_wv_h[DMODEL * DMODEL];
__device__ __align__(256) __nv_bfloat16 g_wv_l[DMODEL * DMODEL];
__device__ __align__(256) __nv_bfloat16 g_wo_h[DMODEL * DMODEL];
__device__ __align__(256) __nv_bfloat16 g_wo_l[DMODEL * DMODEL];

// ---------------- PTX helpers ----------------
__device__ __forceinline__ uint32_t smem_u32(const void* p) {
    uint32_t a;
    asm("{ .reg .u64 t; cvta.to.shared.u64 t, %1; cvt.u32.u64 %0, t; }" : "=r"(a) : "l"(p));
    return a;
}
__device__ __forceinline__ void cpa16(uint32_t dst, const void* src) {
    asm volatile("cp.async.cg.shared.global [%0], [%1], 16;" :: "r"(dst), "l"(src));
}
__device__ __forceinline__ void cpa16p(uint32_t dst, const void* src, bool ok) {
    int sz = ok ? 16 : 0;
    asm volatile("cp.async.cg.shared.global [%0], [%1], 16, %2;" :: "r"(dst), "l"(src), "r"(sz));
}
#define CP_COMMIT() asm volatile("cp.async.commit_group;")
#define CP_WAIT(N)  asm volatile("cp.async.wait_group %0;" :: "n"(N))

__device__ __forceinline__ void ldsm4(uint32_t& r0, uint32_t& r1, uint32_t& r2, uint32_t& r3,
                                      uint32_t addr) {
    asm volatile("ldmatrix.sync.aligned.m8n8.x4.shared.b16 {%0,%1,%2,%3}, [%4];"
                 : "=r"(r0), "=r"(r1), "=r"(r2), "=r"(r3) : "r"(addr));
}
__device__ __forceinline__ void ldsm4t(uint32_t& r0, uint32_t& r1, uint32_t& r2, uint32_t& r3,
                                       uint32_t addr) {
    asm volatile("ldmatrix.sync.aligned.m8n8.x4.trans.shared.b16 {%0,%1,%2,%3}, [%4];"
                 : "=r"(r0), "=r"(r1), "=r"(r2), "=r"(r3) : "r"(addr));
}
__device__ __forceinline__ void mma16816(float* d, const uint32_t* a, uint32_t b0, uint32_t b1) {
    asm volatile(
        "mma.sync.aligned.m16n8k16.row.col.f32.bf16.bf16.f32 "
        "{%0,%1,%2,%3}, {%4,%5,%6,%7}, {%8,%9}, {%0,%1,%2,%3};"
        : "+f"(d[0]), "+f"(d[1]), "+f"(d[2]), "+f"(d[3])
        : "r"(a[0]), "r"(a[1]), "r"(a[2]), "r"(a[3]), "r"(b0), "r"(b1));
}

__device__ __forceinline__ void split_one(float x, __nv_bfloat16& h, __nv_bfloat16& l) {
    h = __float2bfloat16(x);
    l = __float2bfloat16(x - __bfloat162float(h));
}
__device__ __forceinline__ void split_pack(float a, float b, uint32_t& H, uint32_t& L) {
    __nv_bfloat16 ah = __float2bfloat16(a), bh = __float2bfloat16(b);
    float ar = a - __bfloat162float(ah), br = b - __bfloat162float(bh);
    __nv_bfloat162 hh; hh.x = ah; hh.y = bh;
    __nv_bfloat162 ll; ll.x = __float2bfloat16(ar); ll.y = __float2bfloat16(br);
    H = *(uint32_t*)&hh;
    L = *(uint32_t*)&ll;
}

// ---------------- prep: RoPE + split rope'd AND raw hidden in one pass ----------------
__global__ void prep_kernel(const float* __restrict__ x,
                            __nv_bfloat16* __restrict__ qh, __nv_bfloat16* __restrict__ ql,
                            __nv_bfloat16* __restrict__ hh, __nv_bfloat16* __restrict__ hl) {
    const int NP = MROWS * DMODEL / 2;
    int idx = blockIdx.x * blockDim.x + threadIdx.x;
    if (idx >= NP) return;
    int row = idx / (DMODEL / 2);
    int rem = idx % (DMODEL / 2);
    int h = rem / 32;
    int i = rem % 32;
    int s = row % SEQ;
    float inv = exp2f(-(float)i * (0.03125f * 13.28771238f));
    float sn, cs;
    sincosf((float)s * inv, &sn, &cs);
    int base = row * DMODEL + h * DH;
    float x1 = x[base + i];
    float x2 = x[base + 32 + i];
    float y1 = x1 * cs - x2 * sn;
    float y2 = x2 * cs + x1 * sn;
    __nv_bfloat16 a, b;
    split_one(y1, a, b); qh[base + i] = a;      ql[base + i] = b;
    split_one(y2, a, b); qh[base + 32 + i] = a; ql[base + 32 + i] = b;
    split_one(x1, a, b); hh[base + i] = a;      hl[base + i] = b;
    split_one(x2, a, b); hh[base + 32 + i] = a; hl[base + 32 + i] = b;
}

// ---------------- fused weight transpose + split ----------------
struct WArgs {
    const float* W[4];
    __nv_bfloat16* oh[4];
    __nv_bfloat16* ol[4];
};
__global__ void wtrans_split4(WArgs args) {
    __shared__ float t[32][33];
    int z = blockIdx.z;
    const float* W = args.W[z];
    __nv_bfloat16* oh = args.oh[z];
    __nv_bfloat16* ol = args.ol[z];
    int nb = blockIdx.x * 32, kb = blockIdx.y * 32;
    int tx = threadIdx.x, ty = threadIdx.y;   // (32, 8)
#pragma unroll
    for (int r = 0; r < 32; r += 8)
        t[ty + r][tx] = W[(size_t)(kb + ty + r) * DMODEL + nb + tx];
    __syncthreads();
#pragma unroll
    for (int r = 0; r < 32; r += 8) {
        float x = t[tx][ty + r];
        __nv_bfloat16 h, l;
        split_one(x, h, l);
        size_t o = (size_t)(nb + ty + r) * DMODEL + kb + tx;
        oh[o] = h; ol[o] = l;
    }
}

// ---------------- mma.sync bf16x3 GEMM: 128x256 CTA tile, 512 thr / 16 warps ----------------
#define GBM 128
#define GBN 256
#define GK  768
#define NCH (GK / 64)               // 12
#define A_MAT (128 * 128)           // 16384 B (one 128-row x 128B matrix)
#define B_MAT (256 * 128)           // 32768 B
#define STAGE_BYTES (2 * A_MAT + 2 * B_MAT)   // 98304
#define OFF_B (2 * A_MAT)
#define GEMM_SMEM (2 * STAGE_BYTES) // 196608

struct GemmArgs {
    const __nv_bfloat16* Ah[3];
    const __nv_bfloat16* Al[3];
    const __nv_bfloat16* Bh[3];
    const __nv_bfloat16* Bl[3];
    const float* bias[3];
    float* Cf[3];
    __nv_bfloat16* Ch[3];
    __nv_bfloat16* Cl[3];
    float scale[3];
};

__device__ __forceinline__ void load_chunk(
    uint32_t st,
    const __nv_bfloat16* __restrict__ Ah, const __nv_bfloat16* __restrict__ Al,
    const __nv_bfloat16* __restrict__ Bh, const __nv_bfloat16* __restrict__ Bl,
    int m0, int n0, int kc, int tid)
{
    int k0 = kc * 64;
    // A: 128 rows x 8 16B-chunks = 1024 units, 512 threads -> 2 iters (h & l together)
#pragma unroll
    for (int i = 0; i < 2; i++) {
        int u = tid + i * 512;
        int r = u >> 3, c = u & 7;
        uint32_t off = (uint32_t)(r * 128) + (uint32_t)((c ^ (r & 7)) << 4);
        size_t ga = (size_t)(m0 + r) * GK + k0 + c * 8;
        cpa16(st + off,         Ah + ga);
        cpa16(st + A_MAT + off, Al + ga);
    }
    // B: 256 rows x 8 = 2048 units -> 4 iters
#pragma unroll
    for (int i = 0; i < 4; i++) {
        int u = tid + i * 512;
        int r = u >> 3, c = u & 7;
        uint32_t off = (uint32_t)(r * 128) + (uint32_t)((c ^ (r & 7)) << 4);
        size_t gb = (size_t)(n0 + r) * GK + k0 + c * 8;
        cpa16(st + OFF_B + off,         Bh + gb);
        cpa16(st + OFF_B + B_MAT + off, Bl + gb);
    }
}

__global__ __launch_bounds__(512, 1) void gemm_mma(GemmArgs args)
{
    extern __shared__ __align__(1024) char sm[];
    uint32_t sb = smem_u32(sm);
    int tid = threadIdx.x, lane = tid & 31, warp = tid >> 5;
    int wm = warp >> 2, wn = warp & 3;          // 4 x 4 warp grid; warp tile 32 x 64
    int z = blockIdx.z;
    int m0 = blockIdx.y * GBM, n0 = blockIdx.x * GBN;

    const __nv_bfloat16* Ah = args.Ah[z];
    const __nv_bfloat16* Al = args.Al[z];
    const __nv_bfloat16* Bh = args.Bh[z];
    const __nv_bfloat16* Bl = args.Bl[z];
    const float* bias = args.bias[z];

    float acc[2][8][4];
#pragma unroll
    for (int a = 0; a < 2; a++)
#pragma unroll
        for (int b = 0; b < 8; b++)
#pragma unroll
            for (int c = 0; c < 4; c++) acc[a][b][c] = 0.f;

    load_chunk(sb, Ah, Al, Bh, Bl, m0, n0, 0, tid);
    CP_COMMIT();

    for (int kc = 0; kc < NCH; kc++) {
        if (kc + 1 < NCH) {
            load_chunk(sb + ((kc + 1) & 1) * STAGE_BYTES, Ah, Al, Bh, Bl, m0, n0, kc + 1, tid);
            CP_COMMIT();
            CP_WAIT(1);
        } else {
            CP_WAIT(0);
        }
        __syncthreads();

        uint32_t base = sb + (kc & 1) * STAGE_BYTES;
#pragma unroll
        for (int ks = 0; ks < 4; ks++) {
            int c0 = ks * 2;
            uint32_t ah[2][4], al[2][4];
#pragma unroll
            for (int mt = 0; mt < 2; mt++) {
                int row = wm * 32 + mt * 16 + (lane & 15);
                int ch = c0 + (lane >> 4);
                uint32_t off = (uint32_t)(row * 128) + (uint32_t)(((ch ^ (row & 7))) << 4);
                ldsm4(ah[mt][0], ah[mt][1], ah[mt][2], ah[mt][3], base + off);
                ldsm4(al[mt][0], al[mt][1], al[mt][2], al[mt][3], base + A_MAT + off);
            }
#pragma unroll
            for (int p = 0; p < 4; p++) {
                int row = wn * 64 + p * 16 + (lane & 7) + ((lane >> 4) << 3);
                int ch = c0 + ((lane >> 3) & 1);
                uint32_t off = (uint32_t)(row * 128) + (uint32_t)(((ch ^ (row & 7))) << 4);
                uint32_t b0, b1, b2, b3, c1, c2, c3, c4;
                ldsm4(b0, b1, b2, b3, base + OFF_B + off);
                ldsm4(c1, c2, c3, c4, base + OFF_B + B_MAT + off);
#pragma unroll
                for (int mt = 0; mt < 2; mt++) {
                    mma16816(acc[mt][2 * p],     ah[mt], b0, b1);
                    mma16816(acc[mt][2 * p],     al[mt], b0, b1);
                    mma16816(acc[mt][2 * p],     ah[mt], c1, c2);
                    mma16816(acc[mt][2 * p + 1], ah[mt], b2, b3);
                    mma16816(acc[mt][2 * p + 1], al[mt], b2, b3);
                    mma16816(acc[mt][2 * p + 1], ah[mt], c3, c4);
                }
            }
        }
        __syncthreads();
    }

    float scale = args.scale[z];
    float* Cf = args.Cf[z];
    if (Cf) {
#pragma unroll
        for (int mt = 0; mt < 2; mt++) {
            int row = m0 + wm * 32 + mt * 16 + (lane >> 2);
#pragma unroll
            for (int nt = 0; nt < 8; nt++) {
                int col = n0 + wn * 64 + nt * 8 + 2 * (lane & 3);
                float b0 = bias[col], b1 = bias[col + 1];
                float2 v0 = make_float2((acc[mt][nt][0] + b0) * scale, (acc[mt][nt][1] + b1) * scale);
                float2 v1 = make_float2((acc[mt][nt][2] + b0) * scale, (acc[mt][nt][3] + b1) * scale);
                *(float2*)(Cf + (size_t)row * DMODEL + col) = v0;
                *(float2*)(Cf + (size_t)(row + 8) * DMODEL + col) = v1;
            }
        }
    } else {
        __nv_bfloat16* Ch = args.Ch[z];
        __nv_bfloat16* Cl = args.Cl[z];
#pragma unroll
        for (int mt = 0; mt < 2; mt++) {
            int row = m0 + wm * 32 + mt * 16 + (lane >> 2);
#pragma unroll
            for (int nt = 0; nt < 8; nt++) {
                int col = n0 + wn * 64 + nt * 8 + 2 * (lane & 3);
                float b0 = bias[col], b1 = bias[col + 1];
                uint32_t H, L;
                split_pack((acc[mt][nt][0] + b0) * scale, (acc[mt][nt][1] + b1) * scale, H, L);
                *(uint32_t*)(Ch + (size_t)row * DMODEL + col) = H;
                *(uint32_t*)(Cl + (size_t)row * DMODEL + col) = L;
                split_pack((acc[mt][nt][2] + b0) * scale, (acc[mt][nt][3] + b1) * scale, H, L);
                *(uint32_t*)(Ch + (size_t)(row + 8) * DMODEL + col) = H;
                *(uint32_t*)(Cl + (size_t)(row + 8) * DMODEL + col) = L;
            }
        }
    }
}

// ---------------- tensor-core flash attention (unchanged from R5) ----------------
#define ATT_SMEM (16384 + 2 * 32768)

__device__ __forceinline__ void attn_load_kv(
    uint32_t st,
    const __nv_bfloat16* __restrict__ Kh_, const __nv_bfloat16* __restrict__ Kl_,
    const __nv_bfloat16* __restrict__ Vh_, const __nv_bfloat16* __restrict__ Vl_,
    int rowbase, int colbase, int kstart, int kt, int tid)
{
#pragma unroll
    for (int it = 0; it < 4; it++) {
        int u = tid + it * 128;
        int r = u >> 3, c = u & 7;
        int j = kstart + kt * 64 + r;
        bool ok = ((unsigned)j < (unsigned)SEQ);
        int jj = ok ? j : 0;
        uint32_t off = (uint32_t)(r * 128) + (uint32_t)((c ^ (r & 7)) << 4);
        size_t go = (size_t)(rowbase + jj) * DMODEL + colbase + c * 8;
        cpa16p(st + off,         Kh_ + go, ok);
        cpa16p(st + 8192 + off,  Kl_ + go, ok);
        cpa16p(st + 16384 + off, Vh_ + go, ok);
        cpa16p(st + 24576 + off, Vl_ + go, ok);
    }
}

__global__ __launch_bounds__(128, 1) void attn_mma(
    const __nv_bfloat16* __restrict__ Qh_, const __nv_bfloat16* __restrict__ Ql_,
    const __nv_bfloat16* __restrict__ Kh_, const __nv_bfloat16* __restrict__ Kl_,
    const __nv_bfloat16* __restrict__ Vh_, const __nv_bfloat16* __restrict__ Vl_,
    __nv_bfloat16* __restrict__ Ch_, __nv_bfloat16* __restrict__ Cl_)
{
    extern __shared__ __align__(1024) char sm[];
    uint32_t sb = smem_u32(sm);
    int tid = threadIdx.x, lane = tid & 31, wrp = tid >> 5;
    int q0 = blockIdx.x * 64;
    int rowbase = blockIdx.z * SEQ;
    int colbase = blockIdx.y * DH;
    int kstart = q0 - WIN;

#pragma unroll
    for (int it = 0; it < 4; it++) {
        int u = tid + it * 128;
        int r = u >> 3, c = u & 7;
        uint32_t off = (uint32_t)(r * 128) + (uint32_t)((c ^ (r & 7)) << 4);
        size_t go = (size_t)(rowbase + q0 + r) * DMODEL + colbase + c * 8;
        cpa16(sb + off, Qh_ + go);
        cpa16(sb + 8192 + off, Ql_ + go);
    }
    attn_load_kv(sb + 16384, Kh_, Kl_, Vh_, Vl_, rowbase, colbase, kstart, 0, tid);
    CP_COMMIT();

    float oacc[8][4];
#pragma unroll
    for (int a = 0; a < 8; a++)
#pragma unroll
        for (int b = 0; b < 4; b++) oacc[a][b] = 0.f;
    float l0 = 0.f, l1 = 0.f, m0p = -1e30f, m1p = -1e30f;
    uint32_t qfh[4][4], qfl[4][4];

    for (int kt = 0; kt < 5; kt++) {
        if (kt < 4) {
            attn_load_kv(sb + 16384 + ((kt + 1) & 1) * 32768,
                         Kh_, Kl_, Vh_, Vl_, rowbase, colbase, kstart, kt + 1, tid);
            CP_COMMIT();
            CP_WAIT(1);
        } else {
            CP_WAIT(0);
        }
        __syncthreads();

        if (kt == 0) {
#pragma unroll
            for (int ks = 0; ks < 4; ks++) {
                int row = wrp * 16 + (lane & 15);
                int ch = ks * 2 + (lane >> 4);
                uint32_t off = (uint32_t)(row * 128) + (uint32_t)(((ch ^ (row & 7))) << 4);
                ldsm4(qfh[ks][0], qfh[ks][1], qfh[ks][2], qfh[ks][3], sb + off);
                ldsm4(qfl[ks][0], qfl[ks][1], qfl[ks][2], qfl[ks][3], sb + 8192 + off);
            }
        }

        uint32_t st = sb + 16384 + (kt & 1) * 32768;

        float sacc[8][4];
#pragma unroll
        for (int a = 0; a < 8; a++)
#pragma unroll
            for (int b = 0; b < 4; b++) sacc[a][b] = 0.f;
#pragma unroll
        for (int ks = 0; ks < 4; ks++) {
#pragma unroll
            for (int p = 0; p < 4; p++) {
                int row = p * 16 + (lane & 7) + ((lane >> 4) << 3);
                int ch = ks * 2 + ((lane >> 3) & 1);
                uint32_t off = (uint32_t)(row * 128) + (uint32_t)(((ch ^ (row & 7))) << 4);
                uint32_t kh0, kh1, kh2, kh3, kl0, kl1, kl2, kl3;
                ldsm4(kh0, kh1, kh2, kh3, st + off);
                ldsm4(kl0, kl1, kl2, kl3, st + 8192 + off);
                mma16816(sacc[2 * p],     qfh[ks], kh0, kh1);
                mma16816(sacc[2 * p],     qfl[ks], kh0, kh1);
                mma16816(sacc[2 * p],     qfh[ks], kl0, kl1);
                mma16816(sacc[2 * p + 1], qfh[ks], kh2, kh3);
                mma16816(sacc[2 * p + 1], qfl[ks], kh2, kh3);
                mma16816(sacc[2 * p + 1], qfh[ks], kl2, kl3);
            }
        }

        int i0 = q0 + wrp * 16 + (lane >> 2);
        int i1 = i0 + 8;
        float mt0 = -1e30f, mt1 = -1e30f;
#pragma unroll
        for (int nt = 0; nt < 8; nt++) {
            int j0 = kstart + kt * 64 + nt * 8 + 2 * (lane & 3);
            int j1 = j0 + 1;
            bool u0 = ((unsigned)j0 < (unsigned)SEQ);
            bool u1 = ((unsigned)j1 < (unsigned)SEQ);
            bool v00 = u0 && (j0 > i0 - WIN) && (j0 < i0 + WIN);
            bool v01 = u1 && (j1 > i0 - WIN) && (j1 < i0 + WIN);
            bool v10 = u0 && (j0 > i1 - WIN) && (j0 < i1 + WIN);
            bool v11 = u1 && (j1 > i1 - WIN) && (j1 < i1 + WIN);
            sacc[nt][0] = v00 ? sacc[nt][0] : -1e30f;
            sacc[nt][1] = v01 ? sacc[nt][1] : -1e30f;
            sacc[nt][2] = v10 ? sacc[nt][2] : -1e30f;
            sacc[nt][3] = v11 ? sacc[nt][3] : -1e30f;
            mt0 = fmaxf(mt0, fmaxf(sacc[nt][0], sacc[nt][1]));
            mt1 = fmaxf(mt1, fmaxf(sacc[nt][2], sacc[nt][3]));
        }
        mt0 = fmaxf(mt0, __shfl_xor_sync(0xffffffffu, mt0, 1));
        mt0 = fmaxf(mt0, __shfl_xor_sync(0xffffffffu, mt0, 2));
        mt1 = fmaxf(mt1, __shfl_xor_sync(0xffffffffu, mt1, 1));
        mt1 = fmaxf(mt1, __shfl_xor_sync(0xffffffffu, mt1, 2));
        float mn0 = fmaxf(m0p, mt0), mn1 = fmaxf(m1p, mt1);
        float f0 = __expf(m0p - mn0), f1 = __expf(m1p - mn1);
        m0p = mn0; m1p = mn1;
        l0 *= f0; l1 *= f1;
#pragma unroll
        for (int nt = 0; nt < 8; nt++) {
            oacc[nt][0] *= f0; oacc[nt][1] *= f0;
            oacc[nt][2] *= f1; oacc[nt][3] *= f1;
        }

        uint32_t pa[4][4], pla[4][4];
#pragma unroll
        for (int s2 = 0; s2 < 4; s2++) {
            int nt0 = 2 * s2, nt1 = nt0 + 1;
            float p00 = __expf(sacc[nt0][0] - mn0), p01 = __expf(sacc[nt0][1] - mn0);
            float p02 = __expf(sacc[nt0][2] - mn1), p03 = __expf(sacc[nt0][3] - mn1);
            float p10 = __expf(sacc[nt1][0] - mn0), p11 = __expf(sacc[nt1][1] - mn0);
            float p12 = __expf(sacc[nt1][2] - mn1), p13 = __expf(sacc[nt1][3] - mn1);
            l0 += p00 + p01 + p10 + p11;
            l1 += p02 + p03 + p12 + p13;
            split_pack(p00, p01, pa[s2][0], pla[s2][0]);
            split_pack(p02, p03, pa[s2][1], pla[s2][1]);
            split_pack(p10, p11, pa[s2][2], pla[s2][2]);
            split_pack(p12, p13, pa[s2][3], pla[s2][3]);
        }

#pragma unroll
        for (int s2 = 0; s2 < 4; s2++) {
#pragma unroll
            for (int c = 0; c < 4; c++) {
                int row = s2 * 16 + (lane & 7) + (((lane >> 3) & 1) << 3);
                int ch = 2 * c + (lane >> 4);
                uint32_t off = (uint32_t)(row * 128) + (uint32_t)(((ch ^ (row & 7))) << 4);
                uint32_t vh0, vh1, vh2, vh3, vl0, vl1, vl2, vl3;
                ldsm4t(vh0, vh1, vh2, vh3, st + 16384 + off);
                ldsm4t(vl0, vl1, vl2, vl3, st + 24576 + off);
                mma16816(oacc[2 * c],     pa[s2],  vh0, vh1);
                mma16816(oacc[2 * c],     pla[s2], vh0, vh1);
                mma16816(oacc[2 * c],     pa[s2],  vl0, vl1);
                mma16816(oacc[2 * c + 1], pa[s2],  vh2, vh3);
                mma16816(oacc[2 * c + 1], pla[s2], vh2, vh3);
                mma16816(oacc[2 * c + 1], pa[s2],  vl2, vl3);
            }
        }
        __syncthreads();
    }

    l0 += __shfl_xor_sync(0xffffffffu, l0, 1);
    l0 += __shfl_xor_sync(0xffffffffu, l0, 2);
    l1 += __shfl_xor_sync(0xffffffffu, l1, 1);
    l1 += __shfl_xor_sync(0xffffffffu, l1, 2);
    float inv0 = 1.0f / l0, inv1 = 1.0f / l1;
    int r0 = rowbase + q0 + wrp * 16 + (lane >> 2);
#pragma unroll
    for (int nt = 0; nt < 8; nt++) {
        int col = colbase + nt * 8 + 2 * (lane & 3);
        uint32_t H, L;
        split_pack(oacc[nt][0] * inv0, oacc[nt][1] * inv0, H, L);
        *(uint32_t*)(Ch_ + (size_t)r0 * DMODEL + col) = H;
        *(uint32_t*)(Cl_ + (size_t)r0 * DMODEL + col) = L;
        split_pack(oacc[nt][2] * inv1, oacc[nt][3] * inv1, H, L);
        *(uint32_t*)(Ch_ + (size_t)(r0 + 8) * DMODEL + col) = H;
        *(uint32_t*)(Cl_ + (size_t)(r0 + 8) * DMODEL + col) = L;
    }
}

// ---------------- launcher ----------------
extern "C" void kernel_launch(void* const* d_in, const int* in_sizes, int n_in,
                              void* d_out, int out_size)
{
    const float* hid = (const float*)d_in[0];
    const float* Wq  = (const float*)d_in[1];
    const float* bq  = (const float*)d_in[2];
    const float* Wk  = (const float*)d_in[3];
    const float* bk  = (const float*)d_in[4];
    const float* Wv  = (const float*)d_in[5];
    const float* bv  = (const float*)d_in[6];
    const float* Wo  = (const float*)d_in[7];
    const float* bo  = (const float*)d_in[8];
    float* out = (float*)d_out;

    __nv_bfloat16 *qkh, *qkl, *hih, *hil, *cth, *ctl;
    __nv_bfloat16 *qh, *ql, *kh, *kl, *vh, *vl;
    __nv_bfloat16 *wqh, *wql, *wkh, *wkl, *wvh, *wvl, *woh, *wol;
    cudaGetSymbolAddress((void**)&qkh, g_qk_h);
    cudaGetSymbolAddress((void**)&qkl, g_qk_l);
    cudaGetSymbolAddress((void**)&hih, g_hid_h);
    cudaGetSymbolAddress((void**)&hil, g_hid_l);
    cudaGetSymbolAddress((void**)&cth, g_ctx_h);
    cudaGetSymbolAddress((void**)&ctl, g_ctx_l);
    cudaGetSymbolAddress((void**)&qh,  g_q_h);
    cudaGetSymbolAddress((void**)&ql,  g_q_l);
    cudaGetSymbolAddress((void**)&kh,  g_k_h);
    cudaGetSymbolAddress((void**)&kl,  g_k_l);
    cudaGetSymbolAddress((void**)&vh,  g_v_h);
    cudaGetSymbolAddress((void**)&vl,  g_v_l);
    cudaGetSymbolAddress((void**)&wqh, g_wq_h);
    cudaGetSymbolAddress((void**)&wql, g_wq_l);
    cudaGetSymbolAddress((void**)&wkh, g_wk_h);
    cudaGetSymbolAddress((void**)&wkl, g_wk_l);
    cudaGetSymbolAddress((void**)&wvh, g_wv_h);
    cudaGetSymbolAddress((void**)&wvl, g_wv_l);
    cudaGetSymbolAddress((void**)&woh, g_wo_h);
    cudaGetSymbolAddress((void**)&wol, g_wo_l);

    cudaFuncSetAttribute(gemm_mma, cudaFuncAttributeMaxDynamicSharedMemorySize, GEMM_SMEM);
    cudaFuncSetAttribute(attn_mma, cudaFuncAttributeMaxDynamicSharedMemorySize, ATT_SMEM);

    {
        int NP = MROWS * DMODEL / 2;
        prep_kernel<<<(NP + 255) / 256, 256>>>(hid, qkh, qkl, hih, hil);
    }
    {
        WArgs wa;
        wa.W[0] = Wq; wa.oh[0] = wqh; wa.ol[0] = wql;
        wa.W[1] = Wk; wa.oh[1] = wkh; wa.ol[1] = wkl;
        wa.W[2] = Wv; wa.oh[2] = wvh; wa.ol[2] = wvl;
        wa.W[3] = Wo; wa.oh[3] = woh; wa.ol[3] = wol;
        dim3 g(DMODEL / 32, DMODEL / 32, 4), b(32, 8);
        wtrans_split4<<<g, b>>>(wa);
    }
    {
        GemmArgs a = {};
        a.Ah[0] = qkh; a.Al[0] = qkl; a.Bh[0] = wqh; a.Bl[0] = wql; a.bias[0] = bq;
        a.Cf[0] = nullptr; a.Ch[0] = qh; a.Cl[0] = ql; a.scale[0] = 0.125f;
        a.Ah[1] = qkh; a.Al[1] = qkl; a.Bh[1] = wkh; a.Bl[1] = wkl; a.bias[1] = bk;
        a.Cf[1] = nullptr; a.Ch[1] = kh; a.Cl[1] = kl; a.scale[1] = 1.0f;
        a.Ah[2] = hih; a.Al[2] = hil; a.Bh[2] = wvh; a.Bl[2] = wvl; a.bias[2] = bv;
        a.Cf[2] = nullptr; a.Ch[2] = vh; a.Cl[2] = vl; a.scale[2] = 1.0f;
        dim3 grid(DMODEL / GBN, MROWS / GBM, 3);   // (3, 32, 3)
        gemm_mma<<<grid, 512, GEMM_SMEM>>>(a);
    }
    {
        dim3 grid(SEQ / 64, HEADS, BATCH);
        attn_mma<<<grid, 128, ATT_SMEM>>>(qh, ql, kh, kl, vh, vl, cth, ctl);
    }
    {
        GemmArgs a = {};
        a.Ah[0] = cth; a.Al[0] = ctl; a.Bh[0] = woh; a.Bl[0] = wol; a.bias[0] = bo;
        a.Cf[0] = out; a.scale[0] = 1.0f;
        dim3 grid(DMODEL / GBN, MROWS / GBM, 1);
        gemm_mma<<<grid, 512, GEMM_SMEM>>>(a);
    }
}